// round 14
// baseline (speedup 1.0000x reference)
#include <cuda_runtime.h>
#include <cuda_fp16.h>
#include <cstdint>

// ---------------------------------------------------------------------------
// Problem dims
// ---------------------------------------------------------------------------
#define NIN   128
#define NHID  256
#define NDEC  512
#define NOUT  10
#define BATCH 32
#define NSET  4096

#define TM       128                    // rows per tile
#define NTILES   (BATCH * NSET / TM)    // 1024
#define THREADS  256                    // 8 warps: 2 (row halves of 64) x 4 (col quarters)
#define GRID_ENC 148                    // persistent: 1 CTA per SM

// Weight image: k-chunks of 64, f16 single product. chunk = 32KB.
#define CHUNK_BYTES 32768
#define NCHUNKS     10                  // L1:2  L2:4  L3:4  (contiguous)
#define IMG_BYTES   (NCHUNKS * CHUNK_BYTES)

// SMEM layout (bytes) — total 134144 (1 CTA/SM)
#define SMEM_A     0                    // 128 rows x 512B f16, XOR-swizzled
#define SMEM_W     65536                // 2 slots x 32KB ring
#define SMEM_BIAS  131072               // 3 x 256 floats (all layers, loaded once)
#define SMEM_TOTAL 134144

// ---------------------------------------------------------------------------
// Device globals (static; fully rewritten every launch)
// ---------------------------------------------------------------------------
__device__ __align__(128) uint8_t g_wimg[IMG_BYTES];
__device__ float g_partial[NTILES * 2 * NHID];   // per tile: [half0 256 | half1 256]

// ---------------------------------------------------------------------------
// PTX helpers (baseline sm_80-era PTX only: safe at compute_103 target)
// ---------------------------------------------------------------------------
__device__ __forceinline__ uint32_t smem_u32(const void* p) {
    uint32_t a;
    asm("{ .reg .u64 t; cvta.to.shared.u64 t, %1; cvt.u32.u64 %0, t; }" : "=r"(a) : "l"(p));
    return a;
}

__device__ __forceinline__ void ldsm4(uint32_t r[4], uint32_t addr) {
    asm volatile("ldmatrix.sync.aligned.m8n8.x4.shared.b16 {%0,%1,%2,%3}, [%4];"
        : "=r"(r[0]), "=r"(r[1]), "=r"(r[2]), "=r"(r[3]) : "r"(addr));
}

// f16 inputs, f32 accumulate
__device__ __forceinline__ void mma16f(float c[4], const uint32_t a[4], uint32_t b0, uint32_t b1) {
    asm volatile(
        "mma.sync.aligned.m16n8k16.row.col.f32.f16.f16.f32 "
        "{%0,%1,%2,%3},{%4,%5,%6,%7},{%8,%9},{%0,%1,%2,%3};"
        : "+f"(c[0]), "+f"(c[1]), "+f"(c[2]), "+f"(c[3])
        : "r"(a[0]), "r"(a[1]), "r"(a[2]), "r"(a[3]), "r"(b0), "r"(b1));
}

#define CP16(dst, src) \
    asm volatile("cp.async.cg.shared.global [%0], [%1], 16;" :: "r"(dst), "l"(src))
#define CP_COMMIT() asm volatile("cp.async.commit_group;" ::: "memory")
#define CP_WAIT1()  asm volatile("cp.async.wait_group 1;"  ::: "memory")

// B-image swizzle: rows are 128B (64 f16 k-values); 3-bit mask on bits 4-6,
// strictly below the 128B row stride; applied to the k-offset on store AND load.
__device__ __forceinline__ uint32_t bmask(int n) { return ((uint32_t)n & 7u) << 4; }

// ---------------------------------------------------------------------------
// Weight pre-convert: fp32 W[K,256] -> swizzled f16 image (k64 chunks).
// ---------------------------------------------------------------------------
__global__ void __launch_bounds__(256)
convert_weights(const float* __restrict__ W1, const float* __restrict__ W2,
                const float* __restrict__ W3)
{
    int idx = blockIdx.x * 256 + threadIdx.x;    // 0 .. 81919 (uint32 slots)
    int chunk = idx >> 13;                       // 8192 slots per chunk
    int rem   = idx & 8191;
    int n     = rem >> 5;                        // 0..255
    int s     = rem & 31;                        // uint32 slot within 128B row

    const float* W; int kbase;
    if (chunk < 2)      { W = W1; kbase = chunk * 64; }
    else if (chunk < 6) { W = W2; kbase = (chunk - 2) * 64; }
    else                { W = W3; kbase = (chunk - 6) * 64; }

    // inverse swizzle: stored byte = (k*2) ^ bm  =>  k*2 = (4s) ^ bm
    uint32_t bm = bmask(n);
    int k0 = (int)((((uint32_t)(4 * s)) ^ bm) >> 1);   // even; pair (k0, k0+1)
    float w0 = W[(kbase + k0) * 256 + n];
    float w1 = W[(kbase + k0 + 1) * 256 + n];

    __half h0 = __float2half_rn(w0);
    __half h1 = __float2half_rn(w1);
    uint32_t hi = ((uint32_t)*reinterpret_cast<uint16_t*>(&h1) << 16) |
                   (uint32_t)*reinterpret_cast<uint16_t*>(&h0);

    *(uint32_t*)(g_wimg + (size_t)chunk * CHUNK_BYTES + n * 128 + 4 * s) = hi;
}

// ---------------------------------------------------------------------------
// Encoder: persistent, 1 CTA/SM, TM=128 tiles, 3 fused layers, single f16
// product. 2-slot k64 ring (128 MMAs/warp between barriers); biases preloaded
// once; final-layer partial sums straight to global per warp-half.
// ---------------------------------------------------------------------------
__global__ void __launch_bounds__(THREADS, 1)
encoder_kernel(const float* __restrict__ x,
               const float* __restrict__ b1, const float* __restrict__ b2,
               const float* __restrict__ b3)
{
    extern __shared__ char smem[];
    const uint32_t sb = smem_u32(smem);
    const int tid  = threadIdx.x;
    const int lane = tid & 31;
    const int wid  = tid >> 5;
    const int wm   = wid >> 2;          // 0..1  (row half, 64 rows)
    const int wn   = wid & 3;           // 0..3  (col quarter, 64 cols)
    float* bias_s = (float*)(smem + SMEM_BIAS);   // [3][256]

    // --- prologue: prefetch chunks 0,1 ---
#pragma unroll
    for (int c0 = 0; c0 < 2; c0++) {
        const uint8_t* src = g_wimg + (size_t)c0 * CHUNK_BYTES;
        uint32_t dst = sb + SMEM_W + (uint32_t)c0 * CHUNK_BYTES;
#pragma unroll
        for (int i = 0; i < 8; i++)
            CP16(dst + (tid + i * 256) * 16, src + (tid + i * 256) * 16);
        CP_COMMIT();
    }

    // --- preload all 3 biases once ---
    bias_s[tid]       = b1[tid];
    bias_s[256 + tid] = b2[tid];
    bias_s[512 + tid] = b3[tid];

    // --- per-thread ldmatrix address precompute ---
    uint32_t a_base[4], a_xm[4];
    {
        int r0 = wm * 64 + (lane & 15);
#pragma unroll
        for (int mt = 0; mt < 4; mt++) {
            int r = r0 + mt * 16;
            a_base[mt] = sb + SMEM_A + (uint32_t)(r * 512);
            a_xm[mt]   = ((uint32_t)(r & 7)) << 4;
        }
    }
    const uint32_t a_h16 = (uint32_t)(lane >> 4) * 16;
    uint32_t b_off[4], b_xm[4];
    {
        int n0 = wn * 64 + (lane & 7) + ((lane >> 4) << 3);
#pragma unroll
        for (int q = 0; q < 4; q++) {
            int n = n0 + q * 16;
            b_off[q] = (uint32_t)(n * 128);
            b_xm[q]  = bmask(n);
        }
    }
    const uint32_t b_h16 = ((uint32_t)(lane >> 3) & 1) * 16;

    const int ncs[3] = { 2, 4, 4 };
    const int gg = lane >> 2, t = lane & 3;

    for (int tile = blockIdx.x; tile < NTILES; tile += GRID_ENC) {
        // --- stage x tile [128 x 128] fp32 -> f16 into swizzled A (512B rows) ---
        {
            const float4* xt = (const float4*)(x + (size_t)tile * TM * NIN);
#pragma unroll
            for (int i = tid; i < TM * NIN / 4; i += THREADS) {
                float4 v = xt[i];
                int p = i * 4;
                int r = p >> 7, cc = p & 127;
                uint32_t off = ((uint32_t)(r * 512 + cc * 2)) ^ ((uint32_t)(r & 7) << 4);
                __half2 lo2 = __floats2half2_rn(v.x, v.y);
                __half2 hi2 = __floats2half2_rn(v.z, v.w);
                uint2 u;
                u.x = *reinterpret_cast<uint32_t*>(&lo2);
                u.y = *reinterpret_cast<uint32_t*>(&hi2);
                *(uint2*)(smem + SMEM_A + off) = u;
            }
        }
        __syncthreads();                 // x staged (also covers bias preload on tile 0)

        int g = 0;                       // within-tile chunk index (0..9)
        for (int L = 0; L < 3; L++) {
            const float* bl_s = bias_s + L * 256;

            float c[4][8][4];
#pragma unroll
            for (int mt = 0; mt < 4; mt++)
#pragma unroll
                for (int nt = 0; nt < 8; nt++)
#pragma unroll
                    for (int e = 0; e < 4; e++) c[mt][nt][e] = 0.f;

            const int nc = ncs[L];
            for (int lk = 0; lk < nc; lk++, g++) {
                CP_WAIT1();              // chunk g resident (1 pending: g+1)
                __syncthreads();         // (also orders prev epilogue's A writes)

                const uint32_t wslot = sb + SMEM_W + (uint32_t)(g & 1) * CHUNK_BYTES;
#pragma unroll
                for (int ks = 0; ks < 4; ks++) {     // k64 chunk = 4 k16 steps
                    uint32_t a[4][4];
                    const uint32_t kkA = (uint32_t)(lk * 128 + ks * 32) + a_h16;
#pragma unroll
                    for (int mt = 0; mt < 4; mt++)
                        ldsm4(a[mt], a_base[mt] + (kkA ^ a_xm[mt]));

                    const uint32_t kkB = (uint32_t)(ks * 32) + b_h16;
#pragma unroll
                    for (int q = 0; q < 4; q++) {
                        uint32_t bh[4];
                        ldsm4(bh, wslot + b_off[q] + (kkB ^ b_xm[q]));
                        const int nt0 = 2 * q;
#pragma unroll
                        for (int mt = 0; mt < 4; mt++) {
                            mma16f(c[mt][nt0],     a[mt], bh[0], bh[1]);
                            mma16f(c[mt][nt0 + 1], a[mt], bh[2], bh[3]);
                        }
                    }
                }

                __syncthreads();         // all warps done reading slot g&1
                {                        // refill with chunk (g+2) mod 10 (periodic stream)
                    int nxt = g + 2; if (nxt >= NCHUNKS) nxt -= NCHUNKS;
                    uint32_t dst = sb + SMEM_W + (uint32_t)(g & 1) * CHUNK_BYTES;
                    const uint8_t* src = g_wimg + (size_t)nxt * CHUNK_BYTES;
#pragma unroll
                    for (int i = 0; i < 8; i++)
                        CP16(dst + (tid + i * 256) * 16, src + (tid + i * 256) * 16);
                }
                CP_COMMIT();
            }

            if (L < 2) {
                // epilogue: bias + relu -> f16, rewrite A in place.
                // Ordering vs next layer's MMA reads: next chunk-top __syncthreads.
#pragma unroll
                for (int mt = 0; mt < 4; mt++) {
                    const int r0 = wm * 64 + mt * 16 + gg;
                    const int r1 = r0 + 8;
                    const uint32_t x0 = ((uint32_t)(r0 & 7)) << 4;
                    const uint32_t x1 = ((uint32_t)(r1 & 7)) << 4;
#pragma unroll
                    for (int nt = 0; nt < 8; nt++) {
                        const int col = wn * 64 + nt * 8 + 2 * t;
                        const float bb0 = bl_s[col], bb1 = bl_s[col + 1];
                        __half2 p0 = __floats2half2_rn(
                            fmaxf(c[mt][nt][0] + bb0, 0.f), fmaxf(c[mt][nt][1] + bb1, 0.f));
                        __half2 p1 = __floats2half2_rn(
                            fmaxf(c[mt][nt][2] + bb0, 0.f), fmaxf(c[mt][nt][3] + bb1, 0.f));
                        uint32_t o0 = ((uint32_t)(r0 * 512 + col * 2)) ^ x0;
                        uint32_t o1 = ((uint32_t)(r1 * 512 + col * 2)) ^ x1;
                        *(uint32_t*)(smem + SMEM_A + o0) = *reinterpret_cast<uint32_t*>(&p0);
                        *(uint32_t*)(smem + SMEM_A + o1) = *reinterpret_cast<uint32_t*>(&p1);
                    }
                }
            } else {
                // final: bias + relu + 64-row column sums, straight to global
                // per warp-half (no smem reduce, no barriers; A untouched).
                float* gout = g_partial + (size_t)tile * 2 * NHID + wm * NHID;
#pragma unroll
                for (int nt = 0; nt < 8; nt++) {
                    const int col = wn * 64 + nt * 8 + 2 * t;
                    const float bb0 = bl_s[col], bb1 = bl_s[col + 1];
                    float s0 = 0.f, s1 = 0.f;
#pragma unroll
                    for (int mt = 0; mt < 4; mt++) {
                        s0 += fmaxf(c[mt][nt][0] + bb0, 0.f) + fmaxf(c[mt][nt][2] + bb0, 0.f);
                        s1 += fmaxf(c[mt][nt][1] + bb1, 0.f) + fmaxf(c[mt][nt][3] + bb1, 0.f);
                    }
#pragma unroll
                    for (int off = 16; off >= 4; off >>= 1) {
                        s0 += __shfl_down_sync(0xffffffffu, s0, off);
                        s1 += __shfl_down_sync(0xffffffffu, s1, off);
                    }
                    if (lane < 4) {      // lane == t; full 64-row sums for this warp
                        float2 v2 = make_float2(s0, s1);
                        *(float2*)(gout + col) = v2;
                    }
                }
            }
        }
    }
}

// ---------------------------------------------------------------------------
// Fused decoder: mean->square->d1->d2->d3, one CTA per batch, 512 threads.
// All weight streams k-outer, coalesced row-major. Exact fp32.
// ---------------------------------------------------------------------------
__global__ void __launch_bounds__(512, 1)
decoder_kernel(const float* __restrict__ D1, const float* __restrict__ c1,
               const float* __restrict__ D2, const float* __restrict__ c2,
               const float* __restrict__ D3, const float* __restrict__ c3,
               float* __restrict__ out)
{
    __shared__ float p_s[NHID];
    __shared__ float d1_s[NDEC];
    __shared__ float d2_s[NDEC];
    __shared__ float wred[16 * NOUT];
    const int b = blockIdx.x, tid = threadIdx.x;
    const int lane = tid & 31, wrp = tid >> 5;

    // mean over 32 tiles x 2 halves (deterministic fixed order), p = relu(m*m)
    if (tid < NHID) {
        const int parts = 2 * (NSET / TM);   // 64
        float s = 0.f;
        const float* base = g_partial + (size_t)(b * (NSET / TM)) * 2 * NHID + tid;
#pragma unroll 8
        for (int i = 0; i < parts; i++) s += base[(size_t)i * NHID];
        const float m = s * (1.0f / NSET);
        p_s[tid] = fmaxf(m * m, 0.f);
    }
    __syncthreads();

    {
        float acc = 0.f;
        const float* w = D1 + tid;
#pragma unroll 8
        for (int k = 0; k < NHID; k++) acc += p_s[k] * w[(size_t)k * NDEC];
        d1_s[tid] = fmaxf(acc + c1[tid], 0.f);
    }
    __syncthreads();

    {
        float acc = 0.f;
        const float* w = D2 + tid;
#pragma unroll 8
        for (int k = 0; k < NDEC; k++) acc += d1_s[k] * w[(size_t)k * NDEC];
        d2_s[tid] = fmaxf(acc + c2[tid], 0.f);
    }
    __syncthreads();

    {
        float part[NOUT];
        const float v = d2_s[tid];
        const float* w = D3 + (size_t)tid * NOUT;
#pragma unroll
        for (int o = 0; o < NOUT; o++) part[o] = v * w[o];
#pragma unroll
        for (int off = 16; off >= 1; off >>= 1)
#pragma unroll
            for (int o = 0; o < NOUT; o++)
                part[o] += __shfl_down_sync(0xffffffffu, part[o], off);
        if (lane == 0)
#pragma unroll
            for (int o = 0; o < NOUT; o++) wred[wrp * NOUT + o] = part[o];
    }
    __syncthreads();
    if (tid < NOUT) {
        float s = 0.f;
#pragma unroll
        for (int w = 0; w < 16; w++) s += wred[w * NOUT + tid];
        out[b * NOUT + tid] = c3[tid] + s;
    }
}

// ---------------------------------------------------------------------------
extern "C" void kernel_launch(void* const* d_in, const int* in_sizes, int n_in,
                              void* d_out, int out_size)
{
    (void)in_sizes; (void)n_in; (void)out_size;
    const float* x  = (const float*)d_in[0];
    const float* W1 = (const float*)d_in[1];
    const float* b1 = (const float*)d_in[2];
    const float* W2 = (const float*)d_in[3];
    const float* b2 = (const float*)d_in[4];
    const float* W3 = (const float*)d_in[5];
    const float* b3 = (const float*)d_in[6];
    const float* D1 = (const float*)d_in[7];
    const float* c1 = (const float*)d_in[8];
    const float* D2 = (const float*)d_in[9];
    const float* c2 = (const float*)d_in[10];
    const float* D3 = (const float*)d_in[11];
    const float* c3 = (const float*)d_in[12];

    cudaFuncSetAttribute(encoder_kernel, cudaFuncAttributeMaxDynamicSharedMemorySize, SMEM_TOTAL);

    convert_weights<<<320, 256>>>(W1, W2, W3);
    encoder_kernel<<<GRID_ENC, THREADS, SMEM_TOTAL>>>(x, b1, b2, b3);
    decoder_kernel<<<BATCH, 512>>>(D1, c1, D2, c2, D3, c3, (float*)d_out);
}

// round 15
// speedup vs baseline: 1.0145x; 1.0145x over previous
#include <cuda_runtime.h>
#include <cuda_fp16.h>
#include <cstdint>

// ---------------------------------------------------------------------------
// Problem dims
// ---------------------------------------------------------------------------
#define NIN   128
#define NHID  256
#define NDEC  512
#define NOUT  10
#define BATCH 32
#define NSET  4096

#define TM       128                    // rows per tile
#define NTILES   (BATCH * NSET / TM)    // 1024
#define THREADS  256                    // 8 warps: 2 (row halves of 64) x 4 (col quarters)
#define GRID_ENC 148                    // persistent: 1 CTA per SM

// Weight image: k-chunks of 64, f16 single product. chunk = 32KB.
#define CHUNK_BYTES 32768
#define NCHUNKS     10                  // L1:2  L2:4  L3:4  (contiguous)
#define IMG_BYTES   (NCHUNKS * CHUNK_BYTES)

// SMEM layout (bytes) — total 166912 (1 CTA/SM)
#define SMEM_A     0                    // 128 rows x 512B f16, XOR-swizzled
#define SMEM_W     65536                // 3 slots x 32KB ring
#define SMEM_BIAS  163840               // 3 x 256 floats (all layers, loaded once)
#define SMEM_TOTAL 166912

// ---------------------------------------------------------------------------
// Device globals (static; fully rewritten every launch)
// ---------------------------------------------------------------------------
__device__ __align__(128) uint8_t g_wimg[IMG_BYTES];
__device__ float g_partial[NTILES * 2 * NHID];   // per tile: [half0 256 | half1 256]

// ---------------------------------------------------------------------------
// PTX helpers (baseline sm_80-era PTX only: safe at compute_103 target)
// ---------------------------------------------------------------------------
__device__ __forceinline__ uint32_t smem_u32(const void* p) {
    uint32_t a;
    asm("{ .reg .u64 t; cvta.to.shared.u64 t, %1; cvt.u32.u64 %0, t; }" : "=r"(a) : "l"(p));
    return a;
}

__device__ __forceinline__ void ldsm4(uint32_t r[4], uint32_t addr) {
    asm volatile("ldmatrix.sync.aligned.m8n8.x4.shared.b16 {%0,%1,%2,%3}, [%4];"
        : "=r"(r[0]), "=r"(r[1]), "=r"(r[2]), "=r"(r[3]) : "r"(addr));
}

// f16 inputs, f32 accumulate
__device__ __forceinline__ void mma16f(float c[4], const uint32_t a[4], uint32_t b0, uint32_t b1) {
    asm volatile(
        "mma.sync.aligned.m16n8k16.row.col.f32.f16.f16.f32 "
        "{%0,%1,%2,%3},{%4,%5,%6,%7},{%8,%9},{%0,%1,%2,%3};"
        : "+f"(c[0]), "+f"(c[1]), "+f"(c[2]), "+f"(c[3])
        : "r"(a[0]), "r"(a[1]), "r"(a[2]), "r"(a[3]), "r"(b0), "r"(b1));
}

#define CP16(dst, src) \
    asm volatile("cp.async.cg.shared.global [%0], [%1], 16;" :: "r"(dst), "l"(src))
#define CP_COMMIT() asm volatile("cp.async.commit_group;" ::: "memory")
#define CP_WAIT1()  asm volatile("cp.async.wait_group 1;"  ::: "memory")

// B-image swizzle: rows are 128B (64 f16 k-values); 3-bit mask on bits 4-6,
// strictly below the 128B row stride; applied to the k-offset on store AND load.
__device__ __forceinline__ uint32_t bmask(int n) { return ((uint32_t)n & 7u) << 4; }

// ---------------------------------------------------------------------------
// Weight pre-convert: fp32 W[K,256] -> swizzled f16 image (k64 chunks).
// smem-staged: coalesced global reads (k,n sweep), coalesced packed writes.
// Grid: 80 blocks = 10 chunks x 8 n-groups of 32.
// ---------------------------------------------------------------------------
__global__ void __launch_bounds__(256)
convert_weights(const float* __restrict__ W1, const float* __restrict__ W2,
                const float* __restrict__ W3)
{
    __shared__ float st[64][33];                 // [k][n], padded
    const int b  = blockIdx.x;
    const int c  = b >> 3;                       // chunk 0..9
    const int ng = b & 7;                        // n-group 0..7
    const int tid = threadIdx.x;

    const float* W; int kbase;
    if (c < 2)      { W = W1; kbase = c * 64; }
    else if (c < 6) { W = W2; kbase = (c - 2) * 64; }
    else            { W = W3; kbase = (c - 6) * 64; }
    const int nbase = ng * 32;

    // coalesced read: each pass covers 8 k-rows x 32 n
#pragma unroll
    for (int i = tid; i < 64 * 32; i += 256) {
        int k = i >> 5, n = i & 31;
        st[k][n] = W[(size_t)(kbase + k) * 256 + nbase + n];
    }
    __syncthreads();

    // packed writes: 4 slots per thread, coalesced within 128B n-rows
#pragma unroll
    for (int j = 0; j < 4; j++) {
        int idx = tid + j * 256;                 // 0..1023
        int n = idx >> 5, s = idx & 31;
        const int gn = nbase + n;
        uint32_t bm = bmask(gn);
        int k0 = (int)((((uint32_t)(4 * s)) ^ bm) >> 1);   // even pair (k0, k0+1)
        __half h0 = __float2half_rn(st[k0][n]);
        __half h1 = __float2half_rn(st[k0 + 1][n]);
        uint32_t hi = ((uint32_t)*reinterpret_cast<uint16_t*>(&h1) << 16) |
                       (uint32_t)*reinterpret_cast<uint16_t*>(&h0);
        *(uint32_t*)(g_wimg + (size_t)c * CHUNK_BYTES + gn * 128 + 4 * s) = hi;
    }
}

// ---------------------------------------------------------------------------
// Encoder: persistent, 1 CTA/SM, TM=128 tiles, 3 fused layers, single f16
// product. 3-slot k64 ring, ONE barrier per chunk (wait1 keeps a copy in
// flight). Biases preloaded once; final sums straight to global per warp-half.
// ---------------------------------------------------------------------------
__global__ void __launch_bounds__(THREADS, 1)
encoder_kernel(const float* __restrict__ x,
               const float* __restrict__ b1, const float* __restrict__ b2,
               const float* __restrict__ b3)
{
    extern __shared__ char smem[];
    const uint32_t sb = smem_u32(smem);
    const int tid  = threadIdx.x;
    const int lane = tid & 31;
    const int wid  = tid >> 5;
    const int wm   = wid >> 2;          // 0..1  (row half, 64 rows)
    const int wn   = wid & 3;           // 0..3  (col quarter, 64 cols)
    float* bias_s = (float*)(smem + SMEM_BIAS);   // [3][256]

    // --- prologue: issue chunks g=0,1 into slots 0,1 ---
#pragma unroll
    for (int c0 = 0; c0 < 2; c0++) {
        const uint8_t* src = g_wimg + (size_t)c0 * CHUNK_BYTES;
        uint32_t dst = sb + SMEM_W + (uint32_t)c0 * CHUNK_BYTES;
#pragma unroll
        for (int i = 0; i < 8; i++)
            CP16(dst + (tid + i * 256) * 16, src + (tid + i * 256) * 16);
        CP_COMMIT();
    }

    // --- preload all 3 biases once ---
    bias_s[tid]       = b1[tid];
    bias_s[256 + tid] = b2[tid];
    bias_s[512 + tid] = b3[tid];

    // --- per-thread ldmatrix address precompute ---
    uint32_t a_base[4], a_xm[4];
    {
        int r0 = wm * 64 + (lane & 15);
#pragma unroll
        for (int mt = 0; mt < 4; mt++) {
            int r = r0 + mt * 16;
            a_base[mt] = sb + SMEM_A + (uint32_t)(r * 512);
            a_xm[mt]   = ((uint32_t)(r & 7)) << 4;
        }
    }
    const uint32_t a_h16 = (uint32_t)(lane >> 4) * 16;
    uint32_t b_off[4], b_xm[4];
    {
        int n0 = wn * 64 + (lane & 7) + ((lane >> 4) << 3);
#pragma unroll
        for (int q = 0; q < 4; q++) {
            int n = n0 + q * 16;
            b_off[q] = (uint32_t)(n * 128);
            b_xm[q]  = bmask(n);
        }
    }
    const uint32_t b_h16 = ((uint32_t)(lane >> 3) & 1) * 16;

    const int ncs[3] = { 2, 4, 4 };
    const int gg = lane >> 2, t = lane & 3;

    int g = 0;                           // GLOBAL chunk counter (never reset;
                                         // chunk id = g % 10, slot = g % 3)
    int slot = 0;                        // g % 3, tracked incrementally

    for (int tile = blockIdx.x; tile < NTILES; tile += GRID_ENC) {
        __syncthreads();                 // prior tile's final-layer A reads done

        // --- stage x tile [128 x 128] fp32 -> f16 into swizzled A (512B rows) ---
        {
            const float4* xt = (const float4*)(x + (size_t)tile * TM * NIN);
#pragma unroll
            for (int i = tid; i < TM * NIN / 4; i += THREADS) {
                float4 v = xt[i];
                int p = i * 4;
                int r = p >> 7, cc = p & 127;
                uint32_t off = ((uint32_t)(r * 512 + cc * 2)) ^ ((uint32_t)(r & 7) << 4);
                __half2 lo2 = __floats2half2_rn(v.x, v.y);
                __half2 hi2 = __floats2half2_rn(v.z, v.w);
                uint2 u;
                u.x = *reinterpret_cast<uint32_t*>(&lo2);
                u.y = *reinterpret_cast<uint32_t*>(&hi2);
                *(uint2*)(smem + SMEM_A + off) = u;
            }
        }
        __syncthreads();                 // x staged (also covers bias preload tile 0)

        for (int L = 0; L < 3; L++) {
            const float* bl_s = bias_s + L * 256;

            float c[4][8][4];
#pragma unroll
            for (int mt = 0; mt < 4; mt++)
#pragma unroll
                for (int nt = 0; nt < 8; nt++)
#pragma unroll
                    for (int e = 0; e < 4; e++) c[mt][nt][e] = 0.f;

            const int nc = ncs[L];
            for (int lk = 0; lk < nc; lk++) {
                CP_WAIT1();              // chunk g resident (g+1 may stay in flight)
                __syncthreads();         // all warps past chunk g-1 reads AND
                                         // prev epilogue A-writes ordered

                {                        // issue chunk g+2 into slot (g+2)%3
                    int nxt = g + 2;
                    int nslot = slot + 2; if (nslot >= 3) nslot -= 3;
                    int ncid = nxt % NCHUNKS;
                    uint32_t dst = sb + SMEM_W + (uint32_t)nslot * CHUNK_BYTES;
                    const uint8_t* src = g_wimg + (size_t)ncid * CHUNK_BYTES;
#pragma unroll
                    for (int i = 0; i < 8; i++)
                        CP16(dst + (tid + i * 256) * 16, src + (tid + i * 256) * 16);
                }
                CP_COMMIT();

                const uint32_t wslot = sb + SMEM_W + (uint32_t)slot * CHUNK_BYTES;
#pragma unroll
                for (int ks = 0; ks < 4; ks++) {     // k64 chunk = 4 k16 steps
                    uint32_t a[4][4];
                    const uint32_t kkA = (uint32_t)(lk * 128 + ks * 32) + a_h16;
#pragma unroll
                    for (int mt = 0; mt < 4; mt++)
                        ldsm4(a[mt], a_base[mt] + (kkA ^ a_xm[mt]));

                    const uint32_t kkB = (uint32_t)(ks * 32) + b_h16;
#pragma unroll
                    for (int q = 0; q < 4; q++) {
                        uint32_t bh[4];
                        ldsm4(bh, wslot + b_off[q] + (kkB ^ b_xm[q]));
                        const int nt0 = 2 * q;
#pragma unroll
                        for (int mt = 0; mt < 4; mt++) {
                            mma16f(c[mt][nt0],     a[mt], bh[0], bh[1]);
                            mma16f(c[mt][nt0 + 1], a[mt], bh[2], bh[3]);
                        }
                    }
                }

                g++;
                slot++; if (slot == 3) slot = 0;
            }

            if (L < 2) {
                __syncthreads();         // all warps' MMA reads of A done
                // epilogue: bias + relu -> f16, rewrite A in place.
                // Next layer's chunk-top barrier orders these writes vs reads.
#pragma unroll
                for (int mt = 0; mt < 4; mt++) {
                    const int r0 = wm * 64 + mt * 16 + gg;
                    const int r1 = r0 + 8;
                    const uint32_t x0 = ((uint32_t)(r0 & 7)) << 4;
                    const uint32_t x1 = ((uint32_t)(r1 & 7)) << 4;
#pragma unroll
                    for (int nt = 0; nt < 8; nt++) {
                        const int col = wn * 64 + nt * 8 + 2 * t;
                        const float bb0 = bl_s[col], bb1 = bl_s[col + 1];
                        __half2 p0 = __floats2half2_rn(
                            fmaxf(c[mt][nt][0] + bb0, 0.f), fmaxf(c[mt][nt][1] + bb1, 0.f));
                        __half2 p1 = __floats2half2_rn(
                            fmaxf(c[mt][nt][2] + bb0, 0.f), fmaxf(c[mt][nt][3] + bb1, 0.f));
                        uint32_t o0 = ((uint32_t)(r0 * 512 + col * 2)) ^ x0;
                        uint32_t o1 = ((uint32_t)(r1 * 512 + col * 2)) ^ x1;
                        *(uint32_t*)(smem + SMEM_A + o0) = *reinterpret_cast<uint32_t*>(&p0);
                        *(uint32_t*)(smem + SMEM_A + o1) = *reinterpret_cast<uint32_t*>(&p1);
                    }
                }
            } else {
                // final: bias + relu + 64-row column sums, straight to global
                // per warp-half (no smem reduce; A untouched; tile-top barrier
                // protects A before next staging).
                float* gout = g_partial + (size_t)tile * 2 * NHID + wm * NHID;
#pragma unroll
                for (int nt = 0; nt < 8; nt++) {
                    const int col = wn * 64 + nt * 8 + 2 * t;
                    const float bb0 = bl_s[col], bb1 = bl_s[col + 1];
                    float s0 = 0.f, s1 = 0.f;
#pragma unroll
                    for (int mt = 0; mt < 4; mt++) {
                        s0 += fmaxf(c[mt][nt][0] + bb0, 0.f) + fmaxf(c[mt][nt][2] + bb0, 0.f);
                        s1 += fmaxf(c[mt][nt][1] + bb1, 0.f) + fmaxf(c[mt][nt][3] + bb1, 0.f);
                    }
#pragma unroll
                    for (int off = 16; off >= 4; off >>= 1) {
                        s0 += __shfl_down_sync(0xffffffffu, s0, off);
                        s1 += __shfl_down_sync(0xffffffffu, s1, off);
                    }
                    if (lane < 4) {      // lane == t; full 64-row sums for this warp
                        float2 v2 = make_float2(s0, s1);
                        *(float2*)(gout + col) = v2;
                    }
                }
            }
        }
    }
}

// ---------------------------------------------------------------------------
// Fused decoder: mean->square->d1->d2->d3, one CTA per batch, 512 threads.
// All weight streams k-outer, coalesced row-major. Exact fp32.
// ---------------------------------------------------------------------------
__global__ void __launch_bounds__(512, 1)
decoder_kernel(const float* __restrict__ D1, const float* __restrict__ c1,
               const float* __restrict__ D2, const float* __restrict__ c2,
               const float* __restrict__ D3, const float* __restrict__ c3,
               float* __restrict__ out)
{
    __shared__ float p_s[NHID];
    __shared__ float d1_s[NDEC];
    __shared__ float d2_s[NDEC];
    __shared__ float wred[16 * NOUT];
    const int b = blockIdx.x, tid = threadIdx.x;
    const int lane = tid & 31, wrp = tid >> 5;

    // mean over 32 tiles x 2 halves (deterministic fixed order), p = relu(m*m)
    if (tid < NHID) {
        const int parts = 2 * (NSET / TM);   // 64
        float s = 0.f;
        const float* base = g_partial + (size_t)(b * (NSET / TM)) * 2 * NHID + tid;
#pragma unroll 8
        for (int i = 0; i < parts; i++) s += base[(size_t)i * NHID];
        const float m = s * (1.0f / NSET);
        p_s[tid] = fmaxf(m * m, 0.f);
    }
    __syncthreads();

    {
        float acc = 0.f;
        const float* w = D1 + tid;
#pragma unroll 8
        for (int k = 0; k < NHID; k++) acc += p_s[k] * w[(size_t)k * NDEC];
        d1_s[tid] = fmaxf(acc + c1[tid], 0.f);
    }
    __syncthreads();

    {
        float acc = 0.f;
        const float* w = D2 + tid;
#pragma unroll 8
        for (int k = 0; k < NDEC; k++) acc += d1_s[k] * w[(size_t)k * NDEC];
        d2_s[tid] = fmaxf(acc + c2[tid], 0.f);
    }
    __syncthreads();

    {
        float part[NOUT];
        const float v = d2_s[tid];
        const float* w = D3 + (size_t)tid * NOUT;
#pragma unroll
        for (int o = 0; o < NOUT; o++) part[o] = v * w[o];
#pragma unroll
        for (int off = 16; off >= 1; off >>= 1)
#pragma unroll
            for (int o = 0; o < NOUT; o++)
                part[o] += __shfl_down_sync(0xffffffffu, part[o], off);
        if (lane == 0)
#pragma unroll
            for (int o = 0; o < NOUT; o++) wred[wrp * NOUT + o] = part[o];
    }
    __syncthreads();
    if (tid < NOUT) {
        float s = 0.f;
#pragma unroll
        for (int w = 0; w < 16; w++) s += wred[w * NOUT + tid];
        out[b * NOUT + tid] = c3[tid] + s;
    }
}

// ---------------------------------------------------------------------------
extern "C" void kernel_launch(void* const* d_in, const int* in_sizes, int n_in,
                              void* d_out, int out_size)
{
    (void)in_sizes; (void)n_in; (void)out_size;
    const float* x  = (const float*)d_in[0];
    const float* W1 = (const float*)d_in[1];
    const float* b1 = (const float*)d_in[2];
    const float* W2 = (const float*)d_in[3];
    const float* b2 = (const float*)d_in[4];
    const float* W3 = (const float*)d_in[5];
    const float* b3 = (const float*)d_in[6];
    const float* D1 = (const float*)d_in[7];
    const float* c1 = (const float*)d_in[8];
    const float* D2 = (const float*)d_in[9];
    const float* c2 = (const float*)d_in[10];
    const float* D3 = (const float*)d_in[11];
    const float* c3 = (const float*)d_in[12];

    cudaFuncSetAttribute(encoder_kernel, cudaFuncAttributeMaxDynamicSharedMemorySize, SMEM_TOTAL);

    convert_weights<<<80, 256>>>(W1, W2, W3);
    encoder_kernel<<<GRID_ENC, THREADS, SMEM_TOTAL>>>(x, b1, b2, b3);
    decoder_kernel<<<BATCH, 512>>>(D1, c1, D2, c2, D3, c3, (float*)d_out);
}

// round 16
// speedup vs baseline: 1.0282x; 1.0135x over previous
#include <cuda_runtime.h>
#include <cuda_fp16.h>
#include <cstdint>

// ---------------------------------------------------------------------------
// Problem dims
// ---------------------------------------------------------------------------
#define NIN   128
#define NHID  256
#define NDEC  512
#define NOUT  10
#define BATCH 32
#define NSET  4096

#define TM       128                    // rows per tile
#define NTILES   (BATCH * NSET / TM)    // 1024
#define THREADS  256                    // 8 warps: 2 (row halves of 64) x 4 (col quarters)
#define GRID_ENC 148                    // persistent: 1 CTA per SM

// Weight image: k-chunks of 64, f16 single product. chunk = 32KB.
#define CHUNK_BYTES 32768
#define NCHUNKS     10                  // L1:2  L2:4  L3:4  (contiguous)
#define IMG_BYTES   (NCHUNKS * CHUNK_BYTES)

// SMEM layout (bytes), PREF variant: A 64K | W 3x32K | X 64K | bias 3K = 232448
#define SMEM_A     0
#define SMEM_W     65536
#define SMEM_X     163840
#define SMEM_BIAS_P 229376
#define SMEM_TOTAL_P 232448             // exact 227KB opt-in

// non-PREF fallback (R15 layout): A 64K | W 3x32K | bias 3K
#define SMEM_BIAS_NP 163840
#define SMEM_TOTAL_NP 166912

// ---------------------------------------------------------------------------
// Device globals (static; fully rewritten every launch)
// ---------------------------------------------------------------------------
__device__ __align__(128) uint8_t g_wimg[IMG_BYTES];
__device__ float g_partial[NTILES * 2 * NHID];   // per tile: [half0 256 | half1 256]

// ---------------------------------------------------------------------------
// PTX helpers (baseline sm_80-era PTX only: safe at compute_103 target)
// ---------------------------------------------------------------------------
__device__ __forceinline__ uint32_t smem_u32(const void* p) {
    uint32_t a;
    asm("{ .reg .u64 t; cvta.to.shared.u64 t, %1; cvt.u32.u64 %0, t; }" : "=r"(a) : "l"(p));
    return a;
}

__device__ __forceinline__ void ldsm4(uint32_t r[4], uint32_t addr) {
    asm volatile("ldmatrix.sync.aligned.m8n8.x4.shared.b16 {%0,%1,%2,%3}, [%4];"
        : "=r"(r[0]), "=r"(r[1]), "=r"(r[2]), "=r"(r[3]) : "r"(addr));
}

// f16 inputs, f32 accumulate
__device__ __forceinline__ void mma16f(float c[4], const uint32_t a[4], uint32_t b0, uint32_t b1) {
    asm volatile(
        "mma.sync.aligned.m16n8k16.row.col.f32.f16.f16.f32 "
        "{%0,%1,%2,%3},{%4,%5,%6,%7},{%8,%9},{%0,%1,%2,%3};"
        : "+f"(c[0]), "+f"(c[1]), "+f"(c[2]), "+f"(c[3])
        : "r"(a[0]), "r"(a[1]), "r"(a[2]), "r"(a[3]), "r"(b0), "r"(b1));
}

#define CP16(dst, src) \
    asm volatile("cp.async.cg.shared.global [%0], [%1], 16;" :: "r"(dst), "l"(src))
#define CP_COMMIT() asm volatile("cp.async.commit_group;" ::: "memory")
#define CP_WAIT1()  asm volatile("cp.async.wait_group 1;"  ::: "memory")

// B-image swizzle: rows are 128B (64 f16 k-values); 3-bit mask on bits 4-6,
// strictly below the 128B row stride; applied to the k-offset on store AND load.
__device__ __forceinline__ uint32_t bmask(int n) { return ((uint32_t)n & 7u) << 4; }

// ---------------------------------------------------------------------------
// Weight pre-convert: fp32 W[K,256] -> swizzled f16 image (k64 chunks).
// smem-staged: coalesced global reads, coalesced packed writes.
// ---------------------------------------------------------------------------
__global__ void __launch_bounds__(256)
convert_weights(const float* __restrict__ W1, const float* __restrict__ W2,
                const float* __restrict__ W3)
{
    __shared__ float st[64][33];
    const int b  = blockIdx.x;
    const int c  = b >> 3;                       // chunk 0..9
    const int ng = b & 7;                        // n-group 0..7
    const int tid = threadIdx.x;

    const float* W; int kbase;
    if (c < 2)      { W = W1; kbase = c * 64; }
    else if (c < 6) { W = W2; kbase = (c - 2) * 64; }
    else            { W = W3; kbase = (c - 6) * 64; }
    const int nbase = ng * 32;

#pragma unroll
    for (int i = tid; i < 64 * 32; i += 256) {
        int k = i >> 5, n = i & 31;
        st[k][n] = W[(size_t)(kbase + k) * 256 + nbase + n];
    }
    __syncthreads();

#pragma unroll
    for (int j = 0; j < 4; j++) {
        int idx = tid + j * 256;
        int n = idx >> 5, s = idx & 31;
        const int gn = nbase + n;
        uint32_t bm = bmask(gn);
        int k0 = (int)((((uint32_t)(4 * s)) ^ bm) >> 1);
        __half h0 = __float2half_rn(st[k0][n]);
        __half h1 = __float2half_rn(st[k0 + 1][n]);
        uint32_t hi = ((uint32_t)*reinterpret_cast<uint16_t*>(&h1) << 16) |
                       (uint32_t)*reinterpret_cast<uint16_t*>(&h0);
        *(uint32_t*)(g_wimg + (size_t)c * CHUNK_BYTES + gn * 128 + 4 * s) = hi;
    }
}

// ---------------------------------------------------------------------------
// Encoder: persistent, 1 CTA/SM, TM=128 tiles, 3 fused layers, single f16
// product. 3-slot k64 ring, ONE barrier per chunk. PREF: next tile's x is
// prefetched into fp32 smem scratch via cp.async folded into the layer-3
// weight-refill commit groups; tile-top staging then reads smem, not global.
// ---------------------------------------------------------------------------
template <bool PREF>
__global__ void __launch_bounds__(THREADS, 1)
encoder_kernel(const float* __restrict__ x,
               const float* __restrict__ b1, const float* __restrict__ b2,
               const float* __restrict__ b3)
{
    extern __shared__ char smem[];
    const uint32_t sb = smem_u32(smem);
    const int tid  = threadIdx.x;
    const int lane = tid & 31;
    const int wid  = tid >> 5;
    const int wm   = wid >> 2;          // 0..1  (row half, 64 rows)
    const int wn   = wid & 3;           // 0..3  (col quarter, 64 cols)
    float* bias_s = (float*)(smem + (PREF ? SMEM_BIAS_P : SMEM_BIAS_NP));

    // --- prologue: issue chunks g=0,1 into slots 0,1 ---
#pragma unroll
    for (int c0 = 0; c0 < 2; c0++) {
        const uint8_t* src = g_wimg + (size_t)c0 * CHUNK_BYTES;
        uint32_t dst = sb + SMEM_W + (uint32_t)c0 * CHUNK_BYTES;
#pragma unroll
        for (int i = 0; i < 8; i++)
            CP16(dst + (tid + i * 256) * 16, src + (tid + i * 256) * 16);
        CP_COMMIT();
    }

    // --- preload all 3 biases once ---
    bias_s[tid]       = b1[tid];
    bias_s[256 + tid] = b2[tid];
    bias_s[512 + tid] = b3[tid];

    // --- per-thread ldmatrix address precompute ---
    uint32_t a_base[4], a_xm[4];
    {
        int r0 = wm * 64 + (lane & 15);
#pragma unroll
        for (int mt = 0; mt < 4; mt++) {
            int r = r0 + mt * 16;
            a_base[mt] = sb + SMEM_A + (uint32_t)(r * 512);
            a_xm[mt]   = ((uint32_t)(r & 7)) << 4;
        }
    }
    const uint32_t a_h16 = (uint32_t)(lane >> 4) * 16;
    uint32_t b_off[4], b_xm[4];
    {
        int n0 = wn * 64 + (lane & 7) + ((lane >> 4) << 3);
#pragma unroll
        for (int q = 0; q < 4; q++) {
            int n = n0 + q * 16;
            b_off[q] = (uint32_t)(n * 128);
            b_xm[q]  = bmask(n);
        }
    }
    const uint32_t b_h16 = ((uint32_t)(lane >> 3) & 1) * 16;

    const int ncs[3] = { 2, 4, 4 };
    const int gg = lane >> 2, t = lane & 3;

    int g = 0;                           // GLOBAL chunk counter (chunk = g%10, slot = g%3)
    int slot = 0;
    bool have_pref = false;              // tile's x already in smem scratch?

    for (int tile = blockIdx.x; tile < NTILES; tile += GRID_ENC) {
        __syncthreads();                 // prior tile's final-layer A reads done

        // --- stage x tile [128 x 128] -> f16 swizzled A ---
        if (PREF && have_pref) {
            // from fp32 smem scratch (each thread converts the bytes IT copied)
#pragma unroll
            for (int j = 0; j < 16; j++) {
                int i = tid + j * 256;           // float4 slot 0..4095
                float4 v = *(float4*)(smem + SMEM_X + (size_t)i * 16);
                int p = i * 4;
                int r = p >> 7, cc = p & 127;
                uint32_t off = ((uint32_t)(r * 512 + cc * 2)) ^ ((uint32_t)(r & 7) << 4);
                __half2 lo2 = __floats2half2_rn(v.x, v.y);
                __half2 hi2 = __floats2half2_rn(v.z, v.w);
                uint2 u;
                u.x = *reinterpret_cast<uint32_t*>(&lo2);
                u.y = *reinterpret_cast<uint32_t*>(&hi2);
                *(uint2*)(smem + SMEM_A + off) = u;
            }
        } else {
            const float4* xt = (const float4*)(x + (size_t)tile * TM * NIN);
#pragma unroll
            for (int i0 = tid; i0 < TM * NIN / 4; i0 += THREADS) {
                float4 v = xt[i0];
                int p = i0 * 4;
                int r = p >> 7, cc = p & 127;
                uint32_t off = ((uint32_t)(r * 512 + cc * 2)) ^ ((uint32_t)(r & 7) << 4);
                __half2 lo2 = __floats2half2_rn(v.x, v.y);
                __half2 hi2 = __floats2half2_rn(v.z, v.w);
                uint2 u;
                u.x = *reinterpret_cast<uint32_t*>(&lo2);
                u.y = *reinterpret_cast<uint32_t*>(&hi2);
                *(uint2*)(smem + SMEM_A + off) = u;
            }
        }
        __syncthreads();                 // x staged (also covers bias preload tile 0)

        for (int L = 0; L < 3; L++) {
            const float* bl_s = bias_s + L * 256;

            float c[4][8][4];
#pragma unroll
            for (int mt = 0; mt < 4; mt++)
#pragma unroll
                for (int nt = 0; nt < 8; nt++)
#pragma unroll
                    for (int e = 0; e < 4; e++) c[mt][nt][e] = 0.f;

            const int nc = ncs[L];
            for (int lk = 0; lk < nc; lk++) {
                CP_WAIT1();              // chunk g resident (g+1 may stay in flight)
                __syncthreads();         // chunk g-1 reads done; epilogue A-writes ordered

                {                        // issue chunk g+2 into slot (g+2)%3
                    int nxt = g + 2;
                    int nslot = slot + 2; if (nslot >= 3) nslot -= 3;
                    int ncid = nxt % NCHUNKS;
                    uint32_t dst = sb + SMEM_W + (uint32_t)nslot * CHUNK_BYTES;
                    const uint8_t* src = g_wimg + (size_t)ncid * CHUNK_BYTES;
#pragma unroll
                    for (int i = 0; i < 8; i++)
                        CP16(dst + (tid + i * 256) * 16, src + (tid + i * 256) * 16);

                    if (PREF && L == 2 && lk < 2) {
                        // fold next tile's x (half per group) into this commit group
                        int nt2 = tile + GRID_ENC;
                        if (nt2 < NTILES) {
                            const uint8_t* xsrc = (const uint8_t*)(x + (size_t)nt2 * TM * NIN);
#pragma unroll
                            for (int j = 0; j < 8; j++) {
                                int i = tid + (lk * 8 + j) * 256;   // float4 slot
                                CP16(sb + SMEM_X + (uint32_t)i * 16, xsrc + (size_t)i * 16);
                            }
                        }
                    }
                }
                CP_COMMIT();

                const uint32_t wslot = sb + SMEM_W + (uint32_t)slot * CHUNK_BYTES;
#pragma unroll
                for (int ks = 0; ks < 4; ks++) {     // k64 chunk = 4 k16 steps
                    uint32_t a[4][4];
                    const uint32_t kkA = (uint32_t)(lk * 128 + ks * 32) + a_h16;
#pragma unroll
                    for (int mt = 0; mt < 4; mt++)
                        ldsm4(a[mt], a_base[mt] + (kkA ^ a_xm[mt]));

                    const uint32_t kkB = (uint32_t)(ks * 32) + b_h16;
#pragma unroll
                    for (int q = 0; q < 4; q++) {
                        uint32_t bh[4];
                        ldsm4(bh, wslot + b_off[q] + (kkB ^ b_xm[q]));
                        const int nt0 = 2 * q;
#pragma unroll
                        for (int mt = 0; mt < 4; mt++) {
                            mma16f(c[mt][nt0],     a[mt], bh[0], bh[1]);
                            mma16f(c[mt][nt0 + 1], a[mt], bh[2], bh[3]);
                        }
                    }
                }

                g++;
                slot++; if (slot == 3) slot = 0;
            }

            if (L < 2) {
                __syncthreads();         // all warps' MMA reads of A done
                // epilogue: bias + relu -> f16, rewrite A in place.
#pragma unroll
                for (int mt = 0; mt < 4; mt++) {
                    const int r0 = wm * 64 + mt * 16 + gg;
                    const int r1 = r0 + 8;
                    const uint32_t x0 = ((uint32_t)(r0 & 7)) << 4;
                    const uint32_t x1 = ((uint32_t)(r1 & 7)) << 4;
#pragma unroll
                    for (int nt = 0; nt < 8; nt++) {
                        const int col = wn * 64 + nt * 8 + 2 * t;
                        const float bb0 = bl_s[col], bb1 = bl_s[col + 1];
                        __half2 p0 = __floats2half2_rn(
                            fmaxf(c[mt][nt][0] + bb0, 0.f), fmaxf(c[mt][nt][1] + bb1, 0.f));
                        __half2 p1 = __floats2half2_rn(
                            fmaxf(c[mt][nt][2] + bb0, 0.f), fmaxf(c[mt][nt][3] + bb1, 0.f));
                        uint32_t o0 = ((uint32_t)(r0 * 512 + col * 2)) ^ x0;
                        uint32_t o1 = ((uint32_t)(r1 * 512 + col * 2)) ^ x1;
                        *(uint32_t*)(smem + SMEM_A + o0) = *reinterpret_cast<uint32_t*>(&p0);
                        *(uint32_t*)(smem + SMEM_A + o1) = *reinterpret_cast<uint32_t*>(&p1);
                    }
                }
            } else {
                // final: bias + relu + 64-row column sums, straight to global
                float* gout = g_partial + (size_t)tile * 2 * NHID + wm * NHID;
#pragma unroll
                for (int nt = 0; nt < 8; nt++) {
                    const int col = wn * 64 + nt * 8 + 2 * t;
                    const float bb0 = bl_s[col], bb1 = bl_s[col + 1];
                    float s0 = 0.f, s1 = 0.f;
#pragma unroll
                    for (int mt = 0; mt < 4; mt++) {
                        s0 += fmaxf(c[mt][nt][0] + bb0, 0.f) + fmaxf(c[mt][nt][2] + bb0, 0.f);
                        s1 += fmaxf(c[mt][nt][1] + bb1, 0.f) + fmaxf(c[mt][nt][3] + bb1, 0.f);
                    }
#pragma unroll
                    for (int off = 16; off >= 4; off >>= 1) {
                        s0 += __shfl_down_sync(0xffffffffu, s0, off);
                        s1 += __shfl_down_sync(0xffffffffu, s1, off);
                    }
                    if (lane < 4) {
                        float2 v2 = make_float2(s0, s1);
                        *(float2*)(gout + col) = v2;
                    }
                }
            }
        }
        have_pref = PREF;                // scratch holds next tile's x (if issued)
    }
}

// ---------------------------------------------------------------------------
// Fused decoder: mean->square->d1->d2->d3, one CTA per batch, 512 threads.
// ---------------------------------------------------------------------------
__global__ void __launch_bounds__(512, 1)
decoder_kernel(const float* __restrict__ D1, const float* __restrict__ c1,
               const float* __restrict__ D2, const float* __restrict__ c2,
               const float* __restrict__ D3, const float* __restrict__ c3,
               float* __restrict__ out)
{
    __shared__ float p_s[NHID];
    __shared__ float d1_s[NDEC];
    __shared__ float d2_s[NDEC];
    __shared__ float wred[16 * NOUT];
    const int b = blockIdx.x, tid = threadIdx.x;
    const int lane = tid & 31, wrp = tid >> 5;

    if (tid < NHID) {
        const int parts = 2 * (NSET / TM);   // 64
        float s = 0.f;
        const float* base = g_partial + (size_t)(b * (NSET / TM)) * 2 * NHID + tid;
#pragma unroll 8
        for (int i = 0; i < parts; i++) s += base[(size_t)i * NHID];
        const float m = s * (1.0f / NSET);
        p_s[tid] = fmaxf(m * m, 0.f);
    }
    __syncthreads();

    {
        float acc = 0.f;
        const float* w = D1 + tid;
#pragma unroll 8
        for (int k = 0; k < NHID; k++) acc += p_s[k] * w[(size_t)k * NDEC];
        d1_s[tid] = fmaxf(acc + c1[tid], 0.f);
    }
    __syncthreads();

    {
        float acc = 0.f;
        const float* w = D2 + tid;
#pragma unroll 8
        for (int k = 0; k < NDEC; k++) acc += d1_s[k] * w[(size_t)k * NDEC];
        d2_s[tid] = fmaxf(acc + c2[tid], 0.f);
    }
    __syncthreads();

    {
        float part[NOUT];
        const float v = d2_s[tid];
        const float* w = D3 + (size_t)tid * NOUT;
#pragma unroll
        for (int o = 0; o < NOUT; o++) part[o] = v * w[o];
#pragma unroll
        for (int off = 16; off >= 1; off >>= 1)
#pragma unroll
            for (int o = 0; o < NOUT; o++)
                part[o] += __shfl_down_sync(0xffffffffu, part[o], off);
        if (lane == 0)
#pragma unroll
            for (int o = 0; o < NOUT; o++) wred[wrp * NOUT + o] = part[o];
    }
    __syncthreads();
    if (tid < NOUT) {
        float s = 0.f;
#pragma unroll
        for (int w = 0; w < 16; w++) s += wred[w * NOUT + tid];
        out[b * NOUT + tid] = c3[tid] + s;
    }
}

// ---------------------------------------------------------------------------
extern "C" void kernel_launch(void* const* d_in, const int* in_sizes, int n_in,
                              void* d_out, int out_size)
{
    (void)in_sizes; (void)n_in; (void)out_size;
    const float* x  = (const float*)d_in[0];
    const float* W1 = (const float*)d_in[1];
    const float* b1 = (const float*)d_in[2];
    const float* W2 = (const float*)d_in[3];
    const float* b2 = (const float*)d_in[4];
    const float* W3 = (const float*)d_in[5];
    const float* b3 = (const float*)d_in[6];
    const float* D1 = (const float*)d_in[7];
    const float* c1 = (const float*)d_in[8];
    const float* D2 = (const float*)d_in[9];
    const float* c2 = (const float*)d_in[10];
    const float* D3 = (const float*)d_in[11];
    const float* c3 = (const float*)d_in[12];

    convert_weights<<<80, 256>>>(W1, W2, W3);

    // Try the 227KB prefetch variant; fall back to the proven R15 config.
    cudaError_t e = cudaFuncSetAttribute(
        encoder_kernel<true>, cudaFuncAttributeMaxDynamicSharedMemorySize, SMEM_TOTAL_P);
    if (e == cudaSuccess) {
        encoder_kernel<true><<<GRID_ENC, THREADS, SMEM_TOTAL_P>>>(x, b1, b2, b3);
    } else {
        (void)cudaGetLastError();        // clear sticky error
        cudaFuncSetAttribute(
            encoder_kernel<false>, cudaFuncAttributeMaxDynamicSharedMemorySize, SMEM_TOTAL_NP);
        encoder_kernel<false><<<GRID_ENC, THREADS, SMEM_TOTAL_NP>>>(x, b1, b2, b3);
    }

    decoder_kernel<<<BATCH, 512>>>(D1, c1, D2, c2, D3, c3, (float*)d_out);
}